// round 4
// baseline (speedup 1.0000x reference)
#include <cuda_runtime.h>

// Problem constants
#define NN     4096          // N = B*V
#define BATCH  2048
#define DIM    256
#define NBJ    32            // NN / BN
#define INV_T  14.2857142857142857f   // 1/0.07

// GEMM tiling
#define BM 128
#define BN 128
#define BK 32
#define PAD 2
#define LDS_W (BM + PAD)     // 130, even -> float2-aligned rows

// ---------------- scratch (device globals; no allocations allowed) ----------
__device__ float g_cf[NN * DIM];          // permuted contrast features, 4 MB
__device__ float g_selfdot[NN];           // row max (== self dot for unit rows)
__device__ float g_pos[NN];               // logits[i, partner(i)]
__device__ float g_partS[NN * NBJ];       // per (row, j-block) partial sum exp
__device__ float g_partP[NN * NBJ];       // per (row, j-block) partial sum exp*l
__device__ float g_rowS[NN];
__device__ float g_rowP[NN];

// ---------------- packed fp32x2 helpers (sm_100+ PTX) -----------------------
__device__ __forceinline__ unsigned long long pack2(float x, float y) {
    unsigned long long r;
    asm("mov.b64 %0, {%1, %2};" : "=l"(r) : "f"(x), "f"(y));
    return r;
}
__device__ __forceinline__ void unpack2(unsigned long long v, float& x, float& y) {
    asm("mov.b64 {%0, %1}, %2;" : "=f"(x), "=f"(y) : "l"(v));
}
__device__ __forceinline__ void ffma2(unsigned long long& d,
                                      unsigned long long a,
                                      unsigned long long b) {
    asm volatile("fma.rn.f32x2 %0, %1, %2, %0;" : "+l"(d) : "l"(a), "l"(b));
}

// ---------------- kernel 1: permute + self-dot ------------------------------
// contrast row i = features[i % B, i / B, :]; rows are contiguous in memory.
__global__ void prep_kernel(const float* __restrict__ feats) {
    int gw   = (blockIdx.x * blockDim.x + threadIdx.x) >> 5;  // global warp = row
    int lane = threadIdx.x & 31;
    if (gw >= NN) return;
    int b = gw & (BATCH - 1);
    int v = gw >> 11;                       // i / BATCH  (BATCH = 2^11)
    const float4* src = reinterpret_cast<const float4*>(feats) + (b * 2 + v) * (DIM / 4);
    float4*       dst = reinterpret_cast<float4*>(g_cf) + gw * (DIM / 4);
    float s = 0.f;
#pragma unroll
    for (int q = 0; q < 2; q++) {
        float4 x = src[lane + 32 * q];
        dst[lane + 32 * q] = x;
        s += x.x * x.x + x.y * x.y + x.z * x.z + x.w * x.w;
    }
#pragma unroll
    for (int off = 16; off > 0; off >>= 1)
        s += __shfl_down_sync(0xffffffffu, s, off);
    if (lane == 0) g_selfdot[gw] = s;
}

// ---------------- kernel 2: tiled Gram GEMM + fused softmax-stat epilogue ---
// Block (bj, bi) computes the 128x128 tile of D = CF * CF^T, then reduces
// per-row partials S = sum(exp(l)), P = sum(exp(l)*l) over its 128 columns
// (excluding the positive partner, which is recorded separately).
__global__ __launch_bounds__(256, 2) void gemm_epi_kernel() {
    __shared__ __align__(16) float As[BK][LDS_W];
    __shared__ __align__(16) float Bs[BK][LDS_W];

    const int bi = blockIdx.y, bj = blockIdx.x;
    const int i0 = bi * BM, j0 = bj * BN;
    const int tid = threadIdx.x;
    const int tx = tid & 15, ty = tid >> 4;   // 16x16 threads, 8x8 tile each

    unsigned long long acc[8][4];             // 8 rows x 4 float2-pairs (8 cols)
#pragma unroll
    for (int m = 0; m < 8; m++)
#pragma unroll
        for (int n = 0; n < 4; n++) acc[m][n] = 0ULL;

    const float4* cf4 = reinterpret_cast<const float4*>(g_cf);

    for (int k0 = 0; k0 < DIM; k0 += BK) {
        // cooperative load: 128 rows x 32 k, stored k-major (transposed)
#pragma unroll
        for (int q = 0; q < 4; q++) {
            int slot = tid + 256 * q;         // 0..1023
            int row  = slot >> 3;             // 0..127
            int quad = slot & 7;              // 0..7 (float4 within 32-k chunk)
            float4 a = cf4[(i0 + row) * (DIM / 4) + (k0 >> 2) + quad];
            As[quad * 4 + 0][row] = a.x;
            As[quad * 4 + 1][row] = a.y;
            As[quad * 4 + 2][row] = a.z;
            As[quad * 4 + 3][row] = a.w;
            float4 c = cf4[(j0 + row) * (DIM / 4) + (k0 >> 2) + quad];
            Bs[quad * 4 + 0][row] = c.x;
            Bs[quad * 4 + 1][row] = c.y;
            Bs[quad * 4 + 2][row] = c.z;
            Bs[quad * 4 + 3][row] = c.w;
        }
        __syncthreads();

#pragma unroll
        for (int k = 0; k < BK; k++) {
            // a-frag: 4x float2 (broadcast across the 16 tx lanes)
            const float2* arow = reinterpret_cast<const float2*>(&As[k][ty * 8]);
            const float2* brow = reinterpret_cast<const float2*>(&Bs[k][tx * 8]);
            float a[8];
            unsigned long long bb[4];
#pragma unroll
            for (int p = 0; p < 4; p++) {
                float2 av = arow[p];
                a[2 * p] = av.x; a[2 * p + 1] = av.y;
                float2 bv = brow[p];
                bb[p] = pack2(bv.x, bv.y);
            }
#pragma unroll
            for (int m = 0; m < 8; m++) {
                unsigned long long aa = pack2(a[m], a[m]);
#pragma unroll
                for (int n = 0; n < 4; n++) ffma2(acc[m][n], aa, bb[n]);
            }
        }
        __syncthreads();
    }

    // -------- epilogue: per-row exp stats over this block's 128 columns -----
#pragma unroll
    for (int m = 0; m < 8; m++) {
        const int i  = i0 + ty * 8 + m;
        const float mi = g_selfdot[i];
        const int partner = (i < BATCH) ? i + BATCH : i - BATCH;
        float S = 0.f, P = 0.f;
#pragma unroll
        for (int n = 0; n < 4; n++) {
            float dx, dy;
            unpack2(acc[m][n], dx, dy);
            int j = j0 + tx * 8 + n * 2;
            float l0 = (dx - mi) * INV_T;
            if (j == partner) {
                g_pos[i] = l0;
            } else {
                float e = __expf(l0);
                S += e; P += e * l0;
            }
            float l1 = (dy - mi) * INV_T;
            if (j + 1 == partner) {
                g_pos[i] = l1;
            } else {
                float e = __expf(l1);
                S += e; P += e * l1;
            }
        }
        // reduce across the 16 tx lanes (half-warp groups)
#pragma unroll
        for (int off = 8; off > 0; off >>= 1) {
            S += __shfl_down_sync(0xffffffffu, S, off, 16);
            P += __shfl_down_sync(0xffffffffu, P, off, 16);
        }
        if (tx == 0) {
            g_partS[i * NBJ + bj] = S;
            g_partP[i * NBJ + bj] = P;
        }
    }
}

// ---------------- kernel 3: reduce j-block partials per row -----------------
__global__ void reduce_rows_kernel() {
    int r = blockIdx.x * blockDim.x + threadIdx.x;
    if (r >= NN) return;
    float s = 0.f, p = 0.f;
#pragma unroll
    for (int q = 0; q < NBJ; q++) {
        s += g_partS[r * NBJ + q];
        p += g_partP[r * NBJ + q];
    }
    g_rowS[r] = s;
    g_rowP[r] = p;
}

// ---------------- kernel 4: EMA buffer + final loss -------------------------
__global__ void finalize_kernel(const int* __restrict__ index,
                                const float* __restrict__ u,
                                float* __restrict__ out) {
    __shared__ float red[256];
    int tid = threadIdx.x;
    float local = 0.f;
    for (int i = tid; i < NN; i += 256) {
        int b = i & (BATCH - 1);
        float u_new = 0.1f * u[index[b]] + 0.9f * g_rowS[b];
        local += g_pos[i] - g_rowP[i] / u_new;
    }
    red[tid] = local;
    __syncthreads();
    for (int s = 128; s > 0; s >>= 1) {
        if (tid < s) red[tid] += red[tid + s];
        __syncthreads();
    }
    if (tid == 0) out[0] = -red[0] / (float)NN;
}

// ---------------- launch ----------------------------------------------------
extern "C" void kernel_launch(void* const* d_in, const int* in_sizes, int n_in,
                              void* d_out, int out_size) {
    const int*   index = (const int*)d_in[0];
    const float* feats = (const float*)d_in[1];
    const float* u     = (const float*)d_in[2];
    float*       out   = (float*)d_out;

    prep_kernel<<<NN / 8, 256>>>(feats);                 // 8 warps/block
    dim3 grid(NBJ, NN / BM);
    gemm_epi_kernel<<<grid, 256>>>();
    reduce_rows_kernel<<<NN / 256, 256>>>();
    finalize_kernel<<<1, 256>>>(index, u, out);
}

// round 5
// speedup vs baseline: 1.5144x; 1.5144x over previous
#include <cuda_runtime.h>

// Problem constants
#define NN     4096          // N = B*V
#define BATCH  2048
#define DIM    256
#define NBJ    32            // NN / BN  (column blocks per row)
#define INV_T  14.2857142857142857f   // 1/0.07

// GEMM tiling
#define BM 128
#define BN 128
#define BK 32
#define PAD 2
#define LDS_W (BM + PAD)     // 130, even -> float2-aligned rows
#define NTILES 528           // NBJ*(NBJ+1)/2 upper-triangle tiles

// ---------------- scratch (device globals; no allocations allowed) ----------
__device__ float g_cf[NN * DIM];          // permuted contrast features, 4 MB
__device__ float g_selfdot[NN];           // row max (== self dot for unit rows)
__device__ float g_pos[NN];               // logits[i, partner(i)]
__device__ float g_partS[NN * NBJ];       // per (row, j-block) partial sum exp
__device__ float g_partP[NN * NBJ];       // per (row, j-block) partial sum exp*l
__device__ float g_rowS[NN];
__device__ float g_rowP[NN];

// ---------------- packed fp32x2 helpers (sm_100+ PTX) -----------------------
__device__ __forceinline__ unsigned long long pack2(float x, float y) {
    unsigned long long r;
    asm("mov.b64 %0, {%1, %2};" : "=l"(r) : "f"(x), "f"(y));
    return r;
}
__device__ __forceinline__ void unpack2(unsigned long long v, float& x, float& y) {
    asm("mov.b64 {%0, %1}, %2;" : "=f"(x), "=f"(y) : "l"(v));
}
__device__ __forceinline__ void ffma2(unsigned long long& d,
                                      unsigned long long a,
                                      unsigned long long b) {
    asm volatile("fma.rn.f32x2 %0, %1, %2, %0;" : "+l"(d) : "l"(a), "l"(b));
}

// ---------------- kernel 1: permute + self-dot ------------------------------
__global__ void prep_kernel(const float* __restrict__ feats) {
    int gw   = (blockIdx.x * blockDim.x + threadIdx.x) >> 5;  // global warp = row
    int lane = threadIdx.x & 31;
    if (gw >= NN) return;
    int b = gw & (BATCH - 1);
    int v = gw >> 11;                       // i / BATCH  (BATCH = 2^11)
    const float4* src = reinterpret_cast<const float4*>(feats) + (b * 2 + v) * (DIM / 4);
    float4*       dst = reinterpret_cast<float4*>(g_cf) + gw * (DIM / 4);
    float s = 0.f;
#pragma unroll
    for (int q = 0; q < 2; q++) {
        float4 x = src[lane + 32 * q];
        dst[lane + 32 * q] = x;
        s += x.x * x.x + x.y * x.y + x.z * x.z + x.w * x.w;
    }
#pragma unroll
    for (int off = 16; off > 0; off >>= 1)
        s += __shfl_down_sync(0xffffffffu, s, off);
    if (lane == 0) g_selfdot[gw] = s;
}

// ---------------- kernel 2: symmetric tiled Gram GEMM + fused epilogue ------
// Only upper-triangle tiles (p <= q) are computed. Each tile provides:
//   row-pass: stats for rows in block p over columns in block q  -> partS[i][q]
//   col-pass: stats for rows in block q over columns in block p  -> partS[j][p]
//             (uses the transposed tile with the column's self-dot m_j)
__global__ __launch_bounds__(256, 2) void gemm_epi_kernel() {
    __shared__ __align__(16) float As[BK][LDS_W];
    __shared__ __align__(16) float Bs[BK][LDS_W];

    // triangular mapping: idx -> (p, q), p <= q
    int idx = blockIdx.x;
    int q = (int)((sqrtf(8.f * (float)idx + 1.f) - 1.f) * 0.5f);
    while ((q + 1) * (q + 2) / 2 <= idx) q++;
    while (q * (q + 1) / 2 > idx) q--;
    int p = idx - q * (q + 1) / 2;

    const int i0 = p * BM, j0 = q * BN;
    const int tid = threadIdx.x;
    const int tx = tid & 15, ty = tid >> 4;   // 16x16 threads, 8x8 tile each
    const bool has_partner = (q == p + 16);   // partner offset B = 16 blocks

    unsigned long long acc[8][4];             // 8 rows x 4 float2-pairs (8 cols)
#pragma unroll
    for (int m = 0; m < 8; m++)
#pragma unroll
        for (int n = 0; n < 4; n++) acc[m][n] = 0ULL;

    const float4* cf4 = reinterpret_cast<const float4*>(g_cf);

    for (int k0 = 0; k0 < DIM; k0 += BK) {
#pragma unroll
        for (int qq = 0; qq < 4; qq++) {
            int slot = tid + 256 * qq;        // 0..1023
            int row  = slot >> 3;             // 0..127
            int quad = slot & 7;              // float4 within 32-k chunk
            float4 a = cf4[(i0 + row) * (DIM / 4) + (k0 >> 2) + quad];
            As[quad * 4 + 0][row] = a.x;
            As[quad * 4 + 1][row] = a.y;
            As[quad * 4 + 2][row] = a.z;
            As[quad * 4 + 3][row] = a.w;
            float4 c = cf4[(j0 + row) * (DIM / 4) + (k0 >> 2) + quad];
            Bs[quad * 4 + 0][row] = c.x;
            Bs[quad * 4 + 1][row] = c.y;
            Bs[quad * 4 + 2][row] = c.z;
            Bs[quad * 4 + 3][row] = c.w;
        }
        __syncthreads();

#pragma unroll
        for (int k = 0; k < BK; k++) {
            const float2* arow = reinterpret_cast<const float2*>(&As[k][ty * 8]);
            const float2* brow = reinterpret_cast<const float2*>(&Bs[k][tx * 8]);
            float a[8];
            unsigned long long bb[4];
#pragma unroll
            for (int pp = 0; pp < 4; pp++) {
                float2 av = arow[pp];
                a[2 * pp] = av.x; a[2 * pp + 1] = av.y;
                float2 bv = brow[pp];
                bb[pp] = pack2(bv.x, bv.y);
            }
#pragma unroll
            for (int m = 0; m < 8; m++) {
                unsigned long long aa = pack2(a[m], a[m]);
#pragma unroll
                for (int n = 0; n < 4; n++) ffma2(acc[m][n], aa, bb[n]);
            }
        }
        __syncthreads();
    }

    // -------- row-pass: stats for rows i in block p over columns in block q --
#pragma unroll
    for (int m = 0; m < 8; m++) {
        const int i  = i0 + ty * 8 + m;
        const float mi = g_selfdot[i];
        const int partner = i + BATCH;        // valid only when has_partner
        float S = 0.f, P = 0.f;
#pragma unroll
        for (int n = 0; n < 4; n++) {
            float dx, dy;
            unpack2(acc[m][n], dx, dy);
            int j = j0 + tx * 8 + n * 2;
            float l0 = (dx - mi) * INV_T;
            if (has_partner && j == partner) {
                g_pos[i] = l0;
            } else {
                float e = __expf(l0);
                S += e; P += e * l0;
            }
            float l1 = (dy - mi) * INV_T;
            if (has_partner && j + 1 == partner) {
                g_pos[i] = l1;
            } else {
                float e = __expf(l1);
                S += e; P += e * l1;
            }
        }
#pragma unroll
        for (int off = 8; off > 0; off >>= 1) {
            S += __shfl_down_sync(0xffffffffu, S, off, 16);
            P += __shfl_down_sync(0xffffffffu, P, off, 16);
        }
        if (tx == 0) {
            g_partS[i * NBJ + q] = S;
            g_partP[i * NBJ + q] = P;
        }
    }

    // -------- col-pass (off-diagonal only): rows j in block q over cols in p --
    if (p != q) {
        float* Ssm = &As[0][0];               // reuse GEMM smem: 16 x 128 floats
        float* Psm = &Bs[0][0];
#pragma unroll
        for (int n = 0; n < 8; n++) {
            const int j  = j0 + tx * 8 + n;
            const float mj = g_selfdot[j];
            const int partner = j - BATCH;    // valid only when has_partner
            float S = 0.f, P = 0.f;
#pragma unroll
            for (int m = 0; m < 8; m++) {
                float dx, dy;
                unpack2(acc[m][n >> 1], dx, dy);
                float d = (n & 1) ? dy : dx;
                float l = (d - mj) * INV_T;
                int i = i0 + ty * 8 + m;
                if (has_partner && i == partner) {
                    g_pos[j] = l;
                } else {
                    float e = __expf(l);
                    S += e; P += e * l;
                }
            }
            Ssm[ty * BM + tx * 8 + n] = S;
            Psm[ty * BM + tx * 8 + n] = P;
        }
        __syncthreads();
        int c = tid & 127;
        if (tid < 128) {
            float s = 0.f;
#pragma unroll
            for (int r = 0; r < 16; r++) s += Ssm[r * BM + c];
            g_partS[(j0 + c) * NBJ + p] = s;
        } else {
            float s = 0.f;
#pragma unroll
            for (int r = 0; r < 16; r++) s += Psm[r * BM + c];
            g_partP[(j0 + c) * NBJ + p] = s;
        }
    }
}

// ---------------- kernel 3: reduce j-block partials per row -----------------
__global__ void reduce_rows_kernel() {
    int r = blockIdx.x * blockDim.x + threadIdx.x;
    if (r >= NN) return;
    float s = 0.f, pp = 0.f;
#pragma unroll
    for (int c = 0; c < NBJ; c++) {
        s  += g_partS[r * NBJ + c];
        pp += g_partP[r * NBJ + c];
    }
    g_rowS[r] = s;
    g_rowP[r] = pp;
}

// ---------------- kernel 4: EMA buffer + final loss -------------------------
__global__ void finalize_kernel(const int* __restrict__ index,
                                const float* __restrict__ u,
                                float* __restrict__ out) {
    __shared__ float red[256];
    int tid = threadIdx.x;
    float local = 0.f;
    for (int b = tid; b < BATCH; b += 256) {
        float u_new = 0.1f * u[index[b]] + 0.9f * g_rowS[b];
        float inv = __fdividef(1.f, u_new);
        local += g_pos[b]         - g_rowP[b]         * inv
               + g_pos[b + BATCH] - g_rowP[b + BATCH] * inv;
    }
    red[tid] = local;
    __syncthreads();
    for (int s = 128; s > 0; s >>= 1) {
        if (tid < s) red[tid] += red[tid + s];
        __syncthreads();
    }
    if (tid == 0) out[0] = -red[0] / (float)NN;
}

// ---------------- launch ----------------------------------------------------
extern "C" void kernel_launch(void* const* d_in, const int* in_sizes, int n_in,
                              void* d_out, int out_size) {
    const int*   index = (const int*)d_in[0];
    const float* feats = (const float*)d_in[1];
    const float* u     = (const float*)d_in[2];
    float*       out   = (float*)d_out;

    prep_kernel<<<NN / 8, 256>>>(feats);                 // 8 warps/block
    gemm_epi_kernel<<<NTILES, 256>>>();
    reduce_rows_kernel<<<NN / 256, 256>>>();
    finalize_kernel<<<1, 256>>>(index, u, out);
}